// round 10
// baseline (speedup 1.0000x reference)
#include <cuda_runtime.h>
#include <cuda_fp16.h>
#include <cuda_bf16.h>

// Problem constants: shape (2,3,512,512) fp32, KS=5, PAD=2, ALPHA1=0.1, ALPHA2=1.5, EPS=1e-8
#define HH 512
#define WW 512
#define NPLANE 6
#define NPIX (HH * WW)
#define NTOT (NPLANE * NPIX)           // 1,572,864 per tensor

// bilat block: 32x8 threads, each thread computes 4 pixels in y -> 32x32 tile
#define GXB 16                          // 512/32
#define GYB 16                          // 512/32
#define NBLOCKS (GXB * GYB * NPLANE)    // 1536

// __device__ globals are zero-initialized at module load; bilat's last block
// resets them after use, so every graph replay starts clean with NO init kernel.
__device__ int          g_negflag[2];
__device__ unsigned int g_count;
__device__ float        g_partials[NBLOCKS];

#define L2E  1.4426950408889634f
#define NEGK (-5.0f * L2E)             // -(1/(2*alpha1)) * log2(e) = -7.2134752

// spatial exponent (log2 domain) for s = (rel-2)^2 + (dx-2)^2 in {0,1,2,4,5,8}
__device__ __forceinline__ constexpr float offLog2(int s) {
    return -(float)s * (L2E / 3.0f);
}

// ---------------------------------------------------------------------------
__device__ __forceinline__ int reflect(int i) {
    // jnp.pad mode='reflect', pad=2, dim=512:  -1->1, -2->2, 512->510, 513->509
    return (i < 0) ? -i : ((i >= HH) ? (2 * HH - 2 - i) : i);
}

// ---------------------------------------------------------------------------
// "img.min() < 0" <=> any element < 0.  Plain full scan (no same-address polling).
__global__ __launch_bounds__(256) void flag_kernel(const float4* __restrict__ a,
                                                   const float4* __restrict__ b,
                                                   int n4) {
    int fa = 0, fb = 0;
    const int stride = gridDim.x * blockDim.x;
    for (int i = blockIdx.x * blockDim.x + threadIdx.x; i < n4; i += stride) {
        float4 va = a[i];
        float4 vb = b[i];
        fa |= (va.x < 0.f) | (va.y < 0.f) | (va.z < 0.f) | (va.w < 0.f);
        fb |= (vb.x < 0.f) | (vb.y < 0.f) | (vb.z < 0.f) | (vb.w < 0.f);
    }
    if (__any_sync(0xffffffffu, fa) && ((threadIdx.x & 31) == 0)) g_negflag[0] = 1;
    if (__any_sync(0xffffffffu, fb) && ((threadIdx.x & 31) == 0)) g_negflag[1] = 1;
}

// ---------------------------------------------------------------------------
// Fused bilateral(A), bilateral(B), |diff| partial sum, last-block final
// reduction + state reset.  fp16x2 SIMD: lane .x = tensor A, lane .y = tensor
// B; one HSUB2/HMUL2/HFMA2/ex2.f16x2/HADD2/HFMA2 sequence serves BOTH tensors.
// Spatial gaussian folded into the exponent constant (exact reference math).
// Split even/odd-dx accumulators bound fp16 accumulation error.
__global__ __launch_bounds__(256) void bilat_kernel(const float* __restrict__ A,
                                                    const float* __restrict__ B,
                                                    float* __restrict__ out) {
    __shared__ __half2 sT[36][36];      // (.x = A, .y = B), 5.2 KB
    __shared__ float   swarp[8];
    __shared__ int     s_islast;

    const int tx  = threadIdx.x;        // 0..31
    const int ty  = threadIdx.y;        // 0..7
    const int tid = ty * 32 + tx;
    const int x0  = blockIdx.x * 32;
    const int y0  = blockIdx.y * 32;
    const int plane = blockIdx.z;

    const float sclA = g_negflag[0] ? 0.5f : 1.0f;
    const float bseA = g_negflag[0] ? 0.5f : 0.0f;
    const float sclB = g_negflag[1] ? 0.5f : 1.0f;
    const float bseB = g_negflag[1] ? 0.5f : 0.0f;

    const float* __restrict__ Ap = A + plane * NPIX;
    const float* __restrict__ Bp = B + plane * NPIX;

    // cooperative halo load: 36x36 tile (reflect at borders), normalize, pack fp16x2
    for (int idx = tid; idx < 36 * 36; idx += 256) {
        int r  = idx / 36;
        int c  = idx - r * 36;
        int gy = reflect(y0 - 2 + r);
        int gx = reflect(x0 - 2 + c);
        int g  = gy * WW + gx;
        float pa = fmaf(__ldg(Ap + g), sclA, bseA);
        float pb = fmaf(__ldg(Bp + g), sclB, bseB);
        sT[r][c] = __floats2half2_rn(pa, pb);
    }
    __syncthreads();

    const __half2 NEGKH = __floats2half2_rn(NEGK, NEGK);
    __half2 OFFH[6];
    {
        const int sv[6] = {0, 1, 2, 4, 5, 8};
#pragma unroll
        for (int i = 0; i < 6; i++) {
            float o = offLog2(sv[i]);
            OFFH[i] = __floats2half2_rn(o, o);
        }
    }

    // 4 output pixels per thread: tile rows 4ty .. 4ty+3 (smem center rows +2)
    __half2 ctr[4];
#pragma unroll
    for (int o = 0; o < 4; o++) ctr[o] = sT[4 * ty + o + 2][tx + 2];

    __half2 ws0[4], ws1[4], ac0[4], ac1[4];
    const __half2 Z = __floats2half2_rn(0.f, 0.f);
#pragma unroll
    for (int o = 0; o < 4; o++) { ws0[o] = ws1[o] = ac0[o] = ac1[o] = Z; }

#pragma unroll
    for (int dy = 0; dy < 8; dy++) {           // smem rows 4ty+dy
#pragma unroll
        for (int dx = 0; dx < 5; dx++) {
            __half2 p = sT[4 * ty + dy][tx + dx];   // one LDS.32, both tensors
#pragma unroll
            for (int o = 0; o < 4; o++) {
                const int rel = dy - o;            // row offset within o's window
                if (rel < 0 || rel > 4) continue;
                const int s = (rel - 2) * (rel - 2) + (dx - 2) * (dx - 2);
                const int oi = (s == 0) ? 0 : (s == 1) ? 1 : (s == 2) ? 2
                             : (s == 4) ? 3 : (s == 5) ? 4 : 5;

                __half2 d   = __hsub2(p, ctr[o]);
                __half2 t   = __hmul2(d, NEGKH);
                __half2 arg = __hfma2(t, d, OFFH[oi]);   // NEGK*d^2 - off
                __half2 w   = h2exp2(arg);               // ex2.approx.f16x2
                if (dx & 1) {
                    ws1[o] = __hadd2(ws1[o], w);
                    ac1[o] = __hfma2(w, p, ac1[o]);
                } else {
                    ws0[o] = __hadd2(ws0[o], w);
                    ac0[o] = __hfma2(w, p, ac0[o]);
                }
            }
        }
    }

    // finalize in fp32 (EPS is a fp32 no-op in the reference: wsum >= 1 there)
    float v = 0.f;
#pragma unroll
    for (int o = 0; o < 4; o++) {
        float wsa = __low2float(ws0[o])  + __low2float(ws1[o]);
        float wsb = __high2float(ws0[o]) + __high2float(ws1[o]);
        float aca = __low2float(ac0[o])  + __low2float(ac1[o]);
        float acb = __high2float(ac0[o]) + __high2float(ac1[o]);
        float fa = __fdividef(aca, wsa);
        float fb = __fdividef(acb, wsb);
        v += fabsf(fa - fb);
    }

    // deterministic block reduction
#pragma unroll
    for (int o = 16; o > 0; o >>= 1) v += __shfl_down_sync(0xffffffffu, v, o);
    if ((tid & 31) == 0) swarp[tid >> 5] = v;
    __syncthreads();
    if (tid == 0) {
        float t = 0.f;
#pragma unroll
        for (int w = 0; w < 8; w++) t += swarp[w];
        int bidx = (blockIdx.z * gridDim.y + blockIdx.y) * gridDim.x + blockIdx.x;
        g_partials[bidx] = t;
        __threadfence();
        unsigned int done = atomicAdd(&g_count, 1u);
        s_islast = (done == (unsigned int)(NBLOCKS - 1));
    }
    __syncthreads();

    // last block: deterministic final reduction over L2-hot partials, then
    // reset device state so the next graph replay starts clean.
    if (s_islast) {
        float s = 0.f;
#pragma unroll
        for (int i = 0; i < NBLOCKS / 256; i++)     // 6 scalars per thread
            s += g_partials[tid + i * 256];
#pragma unroll
        for (int o = 16; o > 0; o >>= 1) s += __shfl_down_sync(0xffffffffu, s, o);
        if ((tid & 31) == 0) swarp[tid >> 5] = s;
        __syncthreads();
        if (tid == 0) {
            float t = 0.f;
#pragma unroll
            for (int w = 0; w < 8; w++) t += swarp[w];
            out[0] = t * (1.0f / (float)NTOT);
            g_negflag[0] = 0;              // self-clean for next replay
            g_negflag[1] = 0;
            g_count      = 0;
        }
    }
}

// ---------------------------------------------------------------------------
extern "C" void kernel_launch(void* const* d_in, const int* in_sizes, int n_in,
                              void* d_out, int out_size) {
    const float* A = (const float*)d_in[0];   // output
    const float* B = (const float*)d_in[1];   // target
    float* out = (float*)d_out;

    flag_kernel<<<256, 256>>>((const float4*)A, (const float4*)B, NTOT / 4);

    dim3 grid(GXB, GYB, NPLANE);
    dim3 block(32, 8);
    bilat_kernel<<<grid, block>>>(A, B, out);
}

// round 12
// speedup vs baseline: 1.0747x; 1.0747x over previous
#include <cuda_runtime.h>
#include <cuda_bf16.h>

// Problem constants: shape (2,3,512,512) fp32, KS=5, PAD=2, ALPHA1=0.1, ALPHA2=1.5, EPS=1e-8
#define HH 512
#define WW 512
#define NPLANE 6
#define NPIX (HH * WW)
#define NTOT (NPLANE * NPIX)           // 1,572,864 per tensor

// bilat block: 32x8 threads, each thread computes 4 pixels in y -> 32x32 tile
#define GXB 16                          // 512/32
#define GYB 16                          // 512/32
#define NBLOCKS (GXB * GYB * NPLANE)    // 1536

// __device__ globals are zero-initialized at module load; bilat's last block
// resets them after use, so every graph replay starts clean with NO init kernel.
__device__ int          g_negflag[2];
__device__ unsigned int g_count;
__device__ float        g_partials[NBLOCKS];

#define L2E  1.4426950408889634f
#define NEGK (-5.0f * L2E)             // -(1/(2*alpha1)) * log2(e)

typedef unsigned long long u64;

// ---------------------------------------------------------------------------
// packed fp32x2 helpers (Blackwell-native; one op = both tensors, full fp32)
__device__ __forceinline__ u64 pk2(float lo, float hi) {
    u64 r; asm("mov.b64 %0, {%1, %2};" : "=l"(r) : "f"(lo), "f"(hi)); return r;
}
__device__ __forceinline__ void upk2(u64 v, float& lo, float& hi) {
    asm("mov.b64 {%0, %1}, %2;" : "=f"(lo), "=f"(hi) : "l"(v));
}
__device__ __forceinline__ u64 mul2(u64 a, u64 b) {
    u64 r; asm("mul.rn.f32x2 %0, %1, %2;" : "=l"(r) : "l"(a), "l"(b)); return r;
}
__device__ __forceinline__ u64 fma2(u64 a, u64 b, u64 c) {
    u64 r; asm("fma.rn.f32x2 %0, %1, %2, %3;" : "=l"(r) : "l"(a), "l"(b), "l"(c)); return r;
}
__device__ __forceinline__ float ex2f(float x) {
    float y; asm("ex2.approx.ftz.f32 %0, %1;" : "=f"(y) : "f"(x)); return y;
}

__device__ __forceinline__ int reflect(int i) {
    // jnp.pad mode='reflect', pad=2, dim=512:  -1->1, -2->2, 512->510, 513->509
    return (i < 0) ? -i : ((i >= HH) ? (2 * HH - 2 - i) : i);
}

// spatial gaussian e^{-s/3}; exact same result as reference since the
// per-window constant factor exp2(-NEGK*c^2) is common to ALL taps (including
// the self tap, which stays in the loop) and cancels in sum(wp)/sum(w)
__device__ __forceinline__ constexpr float spatialS(int s) {
    return (s == 0) ? 1.0f
         : (s == 1) ? 0.71653131f
         : (s == 2) ? 0.51341712f
         : (s == 4) ? 0.26359714f
         : (s == 5) ? 0.18887560f
         :            0.06948345f;
}

// ---------------------------------------------------------------------------
// "img.min() < 0" <=> any element < 0.  Plain full scan (no same-address polling).
__global__ __launch_bounds__(256) void flag_kernel(const float4* __restrict__ a,
                                                   const float4* __restrict__ b,
                                                   int n4) {
    int fa = 0, fb = 0;
    const int stride = gridDim.x * blockDim.x;
    for (int i = blockIdx.x * blockDim.x + threadIdx.x; i < n4; i += stride) {
        float4 va = a[i];
        float4 vb = b[i];
        fa |= (va.x < 0.f) | (va.y < 0.f) | (va.z < 0.f) | (va.w < 0.f);
        fb |= (vb.x < 0.f) | (vb.y < 0.f) | (vb.z < 0.f) | (vb.w < 0.f);
    }
    if (__any_sync(0xffffffffu, fa) && ((threadIdx.x & 31) == 0)) g_negflag[0] = 1;
    if (__any_sync(0xffffffffu, fb) && ((threadIdx.x & 31) == 0)) g_negflag[1] = 1;
}

// ---------------------------------------------------------------------------
// Fused bilateral(A), bilateral(B), |diff| partial sum, last-block final
// reduction + state reset.  f32x2 packed math: one FFMA2/MUL2 serves both
// tensors at full fp32 precision; EX2 stays scalar fp32 (2 per tap-pair).
// Exponent per tap is a single FFMA2: arg = q + K1[o]*p, q = NEGK*p^2.
// ALL 25 taps go through the same scaled-weight path (self tap included),
// so the common factor exp2(-NEGK*c^2) cancels exactly in the ratio.
__global__ __launch_bounds__(256) void bilat_kernel(const float* __restrict__ A,
                                                    const float* __restrict__ B,
                                                    float* __restrict__ out) {
    __shared__ float2 sT[36][36];       // .x = A value, .y = B value (10.1 KB)
    __shared__ float  swarp[8];
    __shared__ int    s_islast;

    const int tx  = threadIdx.x;        // 0..31
    const int ty  = threadIdx.y;        // 0..7
    const int tid = ty * 32 + tx;
    const int x0  = blockIdx.x * 32;
    const int y0  = blockIdx.y * 32;
    const int plane = blockIdx.z;

    const float sclA = g_negflag[0] ? 0.5f : 1.0f;
    const float bseA = g_negflag[0] ? 0.5f : 0.0f;
    const float sclB = g_negflag[1] ? 0.5f : 1.0f;
    const float bseB = g_negflag[1] ? 0.5f : 0.0f;

    const float* __restrict__ Ap = A + plane * NPIX;
    const float* __restrict__ Bp = B + plane * NPIX;

    // cooperative halo load: 36x36 tile (reflect at borders), normalized at load
    for (int idx = tid; idx < 36 * 36; idx += 256) {
        int r  = idx / 36;
        int c  = idx - r * 36;
        int gy = reflect(y0 - 2 + r);
        int gx = reflect(x0 - 2 + c);
        int g  = gy * WW + gx;
        sT[r][c] = make_float2(fmaf(__ldg(Ap + g), sclA, bseA),
                               fmaf(__ldg(Bp + g), sclB, bseB));
    }
    __syncthreads();

    const u64* __restrict__ sTu = reinterpret_cast<const u64*>(&sT[0][0]);

    const u64 NEGK2 = pk2(NEGK, NEGK);
    u64 S2[6];
    {
        const int sv[6] = {0, 1, 2, 4, 5, 8};
#pragma unroll
        for (int i = 0; i < 6; i++) {
            float s = spatialS(sv[i]);
            S2[i] = pk2(s, s);
        }
    }

    // 4 output pixels per thread: tile rows 4ty .. 4ty+3 (smem center rows +2)
    const int base = ty * 4 * 36 + tx;  // &sT[4ty][tx] in u64 units

    u64 K1[4];                          // -2*NEGK * center (packed A,B)
    u64 ws[4], ac[4];
    const u64 ZERO2 = pk2(0.f, 0.f);
#pragma unroll
    for (int o = 0; o < 4; o++) {
        u64 c  = sTu[base + (o + 2) * 36 + 2];
        K1[o] = mul2(c, pk2(-2.0f * NEGK, -2.0f * NEGK));
        ws[o] = ZERO2;
        ac[o] = ZERO2;
    }

#pragma unroll
    for (int dy = 0; dy < 8; dy++) {           // smem rows 4ty+dy
#pragma unroll
        for (int dx = 0; dx < 5; dx++) {
            u64 p = sTu[base + dy * 36 + dx];      // one LDS.64, both tensors
            u64 q = mul2(mul2(p, p), NEGK2);       // NEGK*p^2, shared across o
#pragma unroll
            for (int o = 0; o < 4; o++) {
                const int rel = dy - o;            // row offset within o's window
                if (rel < 0 || rel > 4) continue;
                const int s = (rel - 2) * (rel - 2) + (dx - 2) * (dx - 2);
                const int oi = (s == 0) ? 0 : (s == 1) ? 1 : (s == 2) ? 2
                             : (s == 4) ? 3 : (s == 5) ? 4 : 5;

                u64 arg = fma2(p, K1[o], q);       // one FFMA2, both tensors
                float alo, ahi;
                upk2(arg, alo, ahi);
                u64 w = pk2(ex2f(alo), ex2f(ahi)); // scaled range weights
                ws[o] = fma2(w, S2[oi], ws[o]);
                ac[o] = fma2(mul2(w, p), S2[oi], ac[o]);
            }
        }
    }

    // common factor exp2(-NEGK*c^2) cancels in the ratio; EPS is a fp32 no-op
    // in the reference (wsum >= 1 there), so plain divide is exact.
    float v = 0.f;
#pragma unroll
    for (int o = 0; o < 4; o++) {
        float wsa, wsb, aca, acb;
        upk2(ws[o], wsa, wsb);
        upk2(ac[o], aca, acb);
        float fa = __fdividef(aca, wsa);
        float fb = __fdividef(acb, wsb);
        v += fabsf(fa - fb);
    }

    // deterministic block reduction
#pragma unroll
    for (int o = 16; o > 0; o >>= 1) v += __shfl_down_sync(0xffffffffu, v, o);
    if ((tid & 31) == 0) swarp[tid >> 5] = v;
    __syncthreads();
    if (tid == 0) {
        float t = 0.f;
#pragma unroll
        for (int w = 0; w < 8; w++) t += swarp[w];
        int bidx = (blockIdx.z * gridDim.y + blockIdx.y) * gridDim.x + blockIdx.x;
        g_partials[bidx] = t;
        __threadfence();
        unsigned int done = atomicAdd(&g_count, 1u);
        s_islast = (done == (unsigned int)(NBLOCKS - 1));
    }
    __syncthreads();

    // last block: deterministic final reduction over L2-hot partials, then
    // reset device state so the next graph replay starts clean.
    if (s_islast) {
        float s = 0.f;
#pragma unroll
        for (int i = 0; i < NBLOCKS / 256; i++)     // 6 scalars per thread
            s += g_partials[tid + i * 256];
#pragma unroll
        for (int o = 16; o > 0; o >>= 1) s += __shfl_down_sync(0xffffffffu, s, o);
        if ((tid & 31) == 0) swarp[tid >> 5] = s;
        __syncthreads();
        if (tid == 0) {
            float t = 0.f;
#pragma unroll
            for (int w = 0; w < 8; w++) t += swarp[w];
            out[0] = t * (1.0f / (float)NTOT);
            g_negflag[0] = 0;              // self-clean for next replay
            g_negflag[1] = 0;
            g_count      = 0;
        }
    }
}

// ---------------------------------------------------------------------------
extern "C" void kernel_launch(void* const* d_in, const int* in_sizes, int n_in,
                              void* d_out, int out_size) {
    const float* A = (const float*)d_in[0];   // output
    const float* B = (const float*)d_in[1];   // target
    float* out = (float*)d_out;

    flag_kernel<<<256, 256>>>((const float4*)A, (const float4*)B, NTOT / 4);

    dim3 grid(GXB, GYB, NPLANE);
    dim3 block(32, 8);
    bilat_kernel<<<grid, block>>>(A, B, out);
}

// round 13
// speedup vs baseline: 1.1350x; 1.0561x over previous
#include <cuda_runtime.h>
#include <cuda_bf16.h>

// Problem constants: shape (2,3,512,512) fp32, KS=5, PAD=2, ALPHA1=0.1, ALPHA2=1.5, EPS=1e-8
#define HH 512
#define WW 512
#define NPLANE 6
#define NPIX (HH * WW)
#define NTOT (NPLANE * NPIX)           // 1,572,864 per tensor

// bilat block: 32x8 threads, each thread computes 2 pixels in y -> 32x16 tile
#define GXB 16                          // 512/32
#define GYB 32                          // 512/16
#define NBLOCKS (GXB * GYB * NPLANE)    // 3072

// __device__ globals are zero-initialized at module load; bilat's last block
// resets them after use, so every graph replay starts clean with NO init kernel.
__device__ int          g_negflag[2];
__device__ unsigned int g_count;
__device__ float        g_partials[NBLOCKS];

#define L2E  1.4426950408889634f
#define NEGK (-5.0f * L2E)             // -(1/(2*alpha1)) * log2(e)

typedef unsigned long long u64;

// ---------------------------------------------------------------------------
// packed fp32x2 helpers (one wide op = both tensors; issue-slot saver)
__device__ __forceinline__ u64 pk2(float lo, float hi) {
    u64 r; asm("mov.b64 %0, {%1, %2};" : "=l"(r) : "f"(lo), "f"(hi)); return r;
}
__device__ __forceinline__ void upk2(u64 v, float& lo, float& hi) {
    asm("mov.b64 {%0, %1}, %2;" : "=f"(lo), "=f"(hi) : "l"(v));
}
__device__ __forceinline__ u64 mul2(u64 a, u64 b) {
    u64 r; asm("mul.rn.f32x2 %0, %1, %2;" : "=l"(r) : "l"(a), "l"(b)); return r;
}
__device__ __forceinline__ u64 fma2(u64 a, u64 b, u64 c) {
    u64 r; asm("fma.rn.f32x2 %0, %1, %2, %3;" : "=l"(r) : "l"(a), "l"(b), "l"(c)); return r;
}
__device__ __forceinline__ float ex2f(float x) {
    float y; asm("ex2.approx.ftz.f32 %0, %1;" : "=f"(y) : "f"(x)); return y;
}

__device__ __forceinline__ int reflect(int i) {
    // jnp.pad mode='reflect', pad=2, dim=512:  -1->1, -2->2, 512->510, 513->509
    return (i < 0) ? -i : ((i >= HH) ? (2 * HH - 2 - i) : i);
}

// spatial gaussian e^{-s/3}; exact same result as reference since the
// per-window constant factor exp2(-NEGK*c^2) is common to ALL taps (self tap
// included) and cancels in sum(wp)/sum(w)
__device__ __forceinline__ constexpr float spatialS(int s) {
    return (s == 0) ? 1.0f
         : (s == 1) ? 0.71653131f
         : (s == 2) ? 0.51341712f
         : (s == 4) ? 0.26359714f
         : (s == 5) ? 0.18887560f
         :            0.06948345f;
}

// ---------------------------------------------------------------------------
// "img.min() < 0" <=> any element < 0.  Plain full scan (no same-address polling).
__global__ __launch_bounds__(256) void flag_kernel(const float4* __restrict__ a,
                                                   const float4* __restrict__ b,
                                                   int n4) {
    int fa = 0, fb = 0;
    const int stride = gridDim.x * blockDim.x;
    for (int i = blockIdx.x * blockDim.x + threadIdx.x; i < n4; i += stride) {
        float4 va = a[i];
        float4 vb = b[i];
        fa |= (va.x < 0.f) | (va.y < 0.f) | (va.z < 0.f) | (va.w < 0.f);
        fb |= (vb.x < 0.f) | (vb.y < 0.f) | (vb.z < 0.f) | (vb.w < 0.f);
    }
    if (__any_sync(0xffffffffu, fa) && ((threadIdx.x & 31) == 0)) g_negflag[0] = 1;
    if (__any_sync(0xffffffffu, fb) && ((threadIdx.x & 31) == 0)) g_negflag[1] = 1;
}

// ---------------------------------------------------------------------------
// Fused bilateral(A), bilateral(B), |diff| partial sum, last-block final
// reduction + state reset.  f32x2 packed math, coarsen-2 in y (light register
// state -> ILP + occupancy), args for both windows batched ahead of the EX2
// burst to keep MUFU fed.
__global__ __launch_bounds__(256) void bilat_kernel(const float* __restrict__ A,
                                                    const float* __restrict__ B,
                                                    float* __restrict__ out) {
    __shared__ float2 sT[20][36];       // .x = A value, .y = B value (5.76 KB)
    __shared__ float  swarp[8];
    __shared__ int    s_islast;

    const int tx  = threadIdx.x;        // 0..31
    const int ty  = threadIdx.y;        // 0..7
    const int tid = ty * 32 + tx;
    const int x0  = blockIdx.x * 32;
    const int y0  = blockIdx.y * 16;
    const int plane = blockIdx.z;

    const float sclA = g_negflag[0] ? 0.5f : 1.0f;
    const float bseA = g_negflag[0] ? 0.5f : 0.0f;
    const float sclB = g_negflag[1] ? 0.5f : 1.0f;
    const float bseB = g_negflag[1] ? 0.5f : 0.0f;

    const float* __restrict__ Ap = A + plane * NPIX;
    const float* __restrict__ Bp = B + plane * NPIX;

    // cooperative halo load: 20x36 tile (reflect at borders), normalized at load
    for (int idx = tid; idx < 20 * 36; idx += 256) {
        int r  = idx / 36;
        int c  = idx - r * 36;
        int gy = reflect(y0 - 2 + r);
        int gx = reflect(x0 - 2 + c);
        int g  = gy * WW + gx;
        sT[r][c] = make_float2(fmaf(__ldg(Ap + g), sclA, bseA),
                               fmaf(__ldg(Bp + g), sclB, bseB));
    }
    __syncthreads();

    const u64* __restrict__ sTu = reinterpret_cast<const u64*>(&sT[0][0]);

    const u64 NEGK2 = pk2(NEGK, NEGK);

    // 2 output pixels per thread: tile rows 2ty, 2ty+1 (smem center rows +2)
    const int base = ty * 2 * 36 + tx;  // &sT[2ty][tx] in u64 units

    u64 K1[2], ws[2], ac[2];
    const u64 ZERO2 = pk2(0.f, 0.f);
#pragma unroll
    for (int o = 0; o < 2; o++) {
        u64 c  = sTu[base + (o + 2) * 36 + 2];
        K1[o] = mul2(c, pk2(-2.0f * NEGK, -2.0f * NEGK));
        ws[o] = ZERO2;
        ac[o] = ZERO2;
    }

#pragma unroll
    for (int dy = 0; dy < 6; dy++) {           // smem rows 2ty+dy
        const bool has0 = (dy <= 4);           // window o=0 uses rel=dy
        const bool has1 = (dy >= 1);           // window o=1 uses rel=dy-1
#pragma unroll
        for (int dx = 0; dx < 5; dx++) {
            u64 p = sTu[base + dy * 36 + dx];      // one LDS.64, both tensors
            u64 q = mul2(mul2(p, p), NEGK2);       // NEGK*p^2, shared across o

            // batch both windows' args, then burst the EX2s (feeds MUFU),
            // then accumulate (independent chains)
            u64 arg0 = 0, arg1 = 0;
            if (has0) arg0 = fma2(p, K1[0], q);
            if (has1) arg1 = fma2(p, K1[1], q);

            float a0l = 0.f, a0h = 0.f, a1l = 0.f, a1h = 0.f;
            if (has0) upk2(arg0, a0l, a0h);
            if (has1) upk2(arg1, a1l, a1h);

            u64 w0 = 0, w1 = 0;
            if (has0) w0 = pk2(ex2f(a0l), ex2f(a0h));
            if (has1) w1 = pk2(ex2f(a1l), ex2f(a1h));

            if (has0) {
                const int s = (dy - 2) * (dy - 2) + (dx - 2) * (dx - 2);
                const float sp = spatialS(s);
                const u64 S = pk2(sp, sp);
                ws[0] = fma2(w0, S, ws[0]);
                ac[0] = fma2(mul2(w0, p), S, ac[0]);
            }
            if (has1) {
                const int s = (dy - 3) * (dy - 3) + (dx - 2) * (dx - 2);
                const float sp = spatialS(s);
                const u64 S = pk2(sp, sp);
                ws[1] = fma2(w1, S, ws[1]);
                ac[1] = fma2(mul2(w1, p), S, ac[1]);
            }
        }
    }

    // common factor exp2(-NEGK*c^2) cancels in the ratio; EPS is a fp32 no-op
    // in the reference (wsum >= 1 there), so plain divide is exact.
    float v = 0.f;
#pragma unroll
    for (int o = 0; o < 2; o++) {
        float wsa, wsb, aca, acb;
        upk2(ws[o], wsa, wsb);
        upk2(ac[o], aca, acb);
        float fa = __fdividef(aca, wsa);
        float fb = __fdividef(acb, wsb);
        v += fabsf(fa - fb);
    }

    // deterministic block reduction
#pragma unroll
    for (int o = 16; o > 0; o >>= 1) v += __shfl_down_sync(0xffffffffu, v, o);
    if ((tid & 31) == 0) swarp[tid >> 5] = v;
    __syncthreads();
    if (tid == 0) {
        float t = 0.f;
#pragma unroll
        for (int w = 0; w < 8; w++) t += swarp[w];
        int bidx = (blockIdx.z * gridDim.y + blockIdx.y) * gridDim.x + blockIdx.x;
        g_partials[bidx] = t;
        __threadfence();
        unsigned int done = atomicAdd(&g_count, 1u);
        s_islast = (done == (unsigned int)(NBLOCKS - 1));
    }
    __syncthreads();

    // last block: deterministic final reduction over L2-hot partials, then
    // reset device state so the next graph replay starts clean.
    if (s_islast) {
        float s = 0.f;
#pragma unroll
        for (int i = 0; i < NBLOCKS / 256; i++)     // 12 scalars per thread
            s += g_partials[tid + i * 256];
#pragma unroll
        for (int o = 16; o > 0; o >>= 1) s += __shfl_down_sync(0xffffffffu, s, o);
        if ((tid & 31) == 0) swarp[tid >> 5] = s;
        __syncthreads();
        if (tid == 0) {
            float t = 0.f;
#pragma unroll
            for (int w = 0; w < 8; w++) t += swarp[w];
            out[0] = t * (1.0f / (float)NTOT);
            g_negflag[0] = 0;              // self-clean for next replay
            g_negflag[1] = 0;
            g_count      = 0;
        }
    }
}

// ---------------------------------------------------------------------------
extern "C" void kernel_launch(void* const* d_in, const int* in_sizes, int n_in,
                              void* d_out, int out_size) {
    const float* A = (const float*)d_in[0];   // output
    const float* B = (const float*)d_in[1];   // target
    float* out = (float*)d_out;

    flag_kernel<<<256, 256>>>((const float4*)A, (const float4*)B, NTOT / 4);

    dim3 grid(GXB, GYB, NPLANE);
    dim3 block(32, 8);
    bilat_kernel<<<grid, block>>>(A, B, out);
}